// round 16
// baseline (speedup 1.0000x reference)
#include <cuda_runtime.h>
#include <cuda_fp16.h>
#include <cstdint>
#include <cstddef>

#define TSEQ 512
#define BATCH 128
#define HDIM 1024
#define NZ 4096
#define VOC 128
#define EDIM 256
#define NBLK 128

// ---------------- static device buffers ----------------
__device__ half  d_U16[(size_t)NZ * HDIM];            // U^T fp16 [n][k], 8 MB
__device__ float d_embW[VOC * NZ];                    // emb@W + b  [v][n], 2 MB
__device__ half  d_A16[2][BATCH * HDIM];              // ping-pong h (fp16, k-tile-permuted)
__device__ float d_S[(size_t)BATCH * TSEQ * HDIM];    // fp32 states, 256 MB
__device__ unsigned g_qcnt[8];                        // [bg][kw] release counters

// ---------------- PTX helpers ----------------
__device__ __forceinline__ unsigned smaddr(const void* p) {
    return (unsigned)__cvta_generic_to_shared(p);
}
__device__ __forceinline__ void cpa16(void* dst, const void* src) {
    asm volatile("cp.async.cg.shared.global [%0], [%1], 16;\n"
                 :: "r"(smaddr(dst)), "l"(src));
}
__device__ __forceinline__ void ldsm_x4(unsigned* r, const void* p) {
    unsigned a = smaddr(p);
    asm volatile("ldmatrix.sync.aligned.m8n8.x4.shared.b16 {%0,%1,%2,%3}, [%4];\n"
                 : "=r"(r[0]), "=r"(r[1]), "=r"(r[2]), "=r"(r[3]) : "r"(a));
}
__device__ __forceinline__ void mma16816(float* d, const unsigned* a, const unsigned* b) {
    asm volatile("mma.sync.aligned.m16n8k16.row.col.f32.f16.f16.f32 "
                 "{%0,%1,%2,%3},{%4,%5,%6,%7},{%8,%9},{%0,%1,%2,%3};\n"
                 : "+f"(d[0]), "+f"(d[1]), "+f"(d[2]), "+f"(d[3])
                 : "r"(a[0]), "r"(a[1]), "r"(a[2]), "r"(a[3]),
                   "r"(b[0]), "r"(b[1]));
}
// A fragment direct load: permuted tile layout makes this 8B-coalesced, .cg = L2-coherent
__device__ __forceinline__ void ldA64(unsigned& lo, unsigned& hi, const half* p) {
    asm volatile("ld.global.cg.v2.u32 {%0,%1}, [%2];"
                 : "=r"(lo), "=r"(hi) : "l"(p));
}
// ---- fast activations: single-instruction MUFU.TANH ----
__device__ __forceinline__ float ftanh(float x) {
    float r; asm("tanh.approx.f32 %0, %1;" : "=f"(r) : "f"(x)); return r;
}
__device__ __forceinline__ float fsig(float x) {
    float r; asm("tanh.approx.f32 %0, %1;" : "=f"(r) : "f"(0.5f * x));
    return fmaf(0.5f, r, 0.5f);
}

// ---------------- prep: embW = emb @ W + b   (128 x 4096, K=256) ----------------
__global__ void __launch_bounds__(256) prep_embW(const float* __restrict__ emb,
                                                 const float* __restrict__ W,
                                                 const float* __restrict__ bias) {
    __shared__ float Ws[EDIM][32];
    const int n0 = blockIdx.x * 32;
    for (int i = threadIdx.x; i < EDIM * 32; i += 256) {
        int e = i >> 5, c = i & 31;
        Ws[e][c] = W[(size_t)e * NZ + n0 + c];
    }
    __syncthreads();
    const int c = threadIdx.x & 31;
    for (int v = threadIdx.x >> 5; v < VOC; v += 8) {
        float a = bias[n0 + c];
        const float* er = emb + v * EDIM;
        #pragma unroll 8
        for (int e = 0; e < EDIM; e++) a += er[e] * Ws[e][c];
        d_embW[v * NZ + n0 + c] = a;
    }
}

// ---------------- prep: U fp32 [k][n] -> d_U16 fp16 [n][k] ----------------
__global__ void __launch_bounds__(256) prep_U(const float* __restrict__ U) {
    __shared__ float tile[32][33];
    const int n0 = blockIdx.x * 32;
    const int k0 = blockIdx.y * 32;
    const int tx = threadIdx.x & 31, ty = threadIdx.x >> 5;
    #pragma unroll
    for (int i = 0; i < 4; i++) {
        int r = ty + i * 8;
        tile[r][tx] = U[(size_t)(k0 + r) * NZ + n0 + tx];
    }
    __syncthreads();
    #pragma unroll
    for (int i = 0; i < 4; i++) {
        int r = ty + i * 8;
        d_U16[(size_t)(n0 + r) * HDIM + k0 + tx] = __float2half_rn(tile[tx][r]);
    }
}

__global__ void init_state() {
    int i = blockIdx.x * blockDim.x + threadIdx.x;
    if (i < BATCH * HDIM) d_A16[0][i] = __float2half_rn(0.f);
    if (blockIdx.x == 0 && threadIdx.x < 8) g_qcnt[threadIdx.x] = 0;
}

// ---------------- persistent LSTM: 64 n-groups x 2 batch-halves ----------------
// Block (ng, bg) owns rows [64bg,64bg+64) x h-cols [16ng,16ng+16).
// 16 warps = 4 M-subs x 4 K-slices. A loaded DIRECTLY to registers via
// ld.global.cg from the k-tile-permuted d_A16 (no A smem at all).
// B (64 z-cols x 1024 k) resident in smem. Partials [64][65][4] -> epilogue.
#define KC 64
#define B_ROWH 1032                             // 1024 + 8 pad halfs
#define B_H    (64 * B_ROWH)                    // 66048 halfs = 132096 B
#define SMEM_TOTAL (B_H * 2 + 64 * 65 * 4 * 4)  // 132096 + 66560 = 198656 B

__global__ void __launch_bounds__(512, 1) lstm_persist(const int* __restrict__ tokens) {
    extern __shared__ __align__(16) half smh[];
    half*  Bs   = smh;                                   // B[64][1032]
    float* part = reinterpret_cast<float*>(smh + B_H);   // [64][65][4]

    const int tid  = threadIdx.x;
    const int bn   = blockIdx.x;
    const int ng   = bn & 63;      // n-group: h-cols [16ng, 16ng+16)
    const int bg   = bn >> 6;      // batch half: rows [64bg, 64bg+64)
    const int lane = tid & 31, wid = tid >> 5;
    const int ms   = wid & 3;      // M-sub: local rows [ms*16, ms*16+16)
    const int kw   = wid >> 2;     // K-slice: k in [kw*256, kw*256+256)
    const int myq  = ng >> 4;      // k-quarter this block's h-cols land in

    // ---- c/h in registers; thread owns 2 elements, fixed for all steps ----
    const int j    = tid & 15;
    const int lr0  = tid >> 4;                 // 0..31
    const int lr1  = lr0 + 32;                 // 32..63
    const int bb0  = bg * 64 + lr0;
    const int bb1  = bg * 64 + lr1;
    const int col  = ng * 16 + j;              // global h-col (unpermuted)
    // permuted within-tile position for d_A16 store
    const int pj   = (j & 1) + 2 * ((j >> 3) & 1) + 2 * (j & 6);
    const int pcol = ng * 16 + pj;
    float c_reg[2] = {0.f, 0.f};
    float h_reg[2] = {0.f, 0.f};

    // ---- B preload ONCE: 64 z-cols x 1024 k = 8192 x 16B ----
    #pragma unroll
    for (int w = 0; w < 16; w++) {
        int i = tid + w * 512;                 // 0..8191
        int ci = i >> 7, seg = i & 127;
        int gcol = (ci >> 4) * HDIM + ng * 16 + (ci & 15);
        cpa16(Bs + ci * B_ROWH + seg * 8, d_U16 + (size_t)gcol * HDIM + seg * 8);
    }
    asm volatile("cp.async.commit_group;\ncp.async.wait_group 0;\n");
    __syncthreads();

    const int bKsel = ((lane >> 3) & 1) * 8;
    const int rowA  = bg * 64 + ms * 16 + (lane >> 2);
    const int kBase = kw * 256 + (lane & 3) * 4;         // permuted-tile offset

    for (int t = 0; t < TSEQ; t++) {
        const int rb = t & 1, wb = rb ^ 1;
        const half* __restrict__ Asrc = d_A16[rb];
        const half* Abase = Asrc + (size_t)rowA * HDIM + kBase;

        // ---- prefetch gate inputs (independent of h) ----
        const int tk0 = __ldg(&tokens[bb0 * TSEQ + t]);
        const int tk1 = __ldg(&tokens[bb1 * TSEQ + t]);
        const float* e0 = d_embW + (size_t)tk0 * NZ + col;
        const float* e1 = d_embW + (size_t)tk1 * NZ + col;
        float ew0i = e0[0], ew0f = e0[HDIM], ew0g = e0[2 * HDIM], ew0o = e0[3 * HDIM];
        float ew1i = e1[0], ew1f = e1[HDIM], ew1g = e1[2 * HDIM], ew1o = e1[3 * HDIM];

        // ---- acquire own (bg, kw): h(t-1) of my rows, quarter kw, at L2 ----
        if (lane == 0) {
            const unsigned target = 16u * (unsigned)t;
            unsigned v;
            asm volatile("ld.acquire.gpu.global.u32 %0, [%1];"
                         : "=r"(v) : "l"(&g_qcnt[bg * 4 + kw]) : "memory");
            while (v < target) {
                __nanosleep(64);
                asm volatile("ld.acquire.gpu.global.u32 %0, [%1];"
                             : "=r"(v) : "l"(&g_qcnt[bg * 4 + kw]) : "memory");
            }
        }
        __syncwarp();

        // ---- A chunk loader: 16 regs (8 x ld.64), fully coalesced, L2-direct ----
        unsigned ab[3][16];
        auto ldA = [&](int ch, unsigned* buf) {
            const half* p = Abase + ch * KC;
            #pragma unroll
            for (int ks = 0; ks < 4; ks++) {
                ldA64(buf[ks * 4 + 0], buf[ks * 4 + 2], p + ks * 16);
                ldA64(buf[ks * 4 + 1], buf[ks * 4 + 3], p + 8 * HDIM + ks * 16);
            }
        };

        float acc[8][4];
        #pragma unroll
        for (int n = 0; n < 8; n++)
            #pragma unroll
            for (int e = 0; e < 4; e++) acc[n][e] = 0.f;

        auto mmaC = [&](const unsigned* buf, int ch) {
            const int kOffB = kw * 256 + ch * KC + bKsel;
            #pragma unroll
            for (int ks = 0; ks < 4; ks++) {
                #pragma unroll
                for (int nt2 = 0; nt2 < 4; nt2++) {
                    unsigned q[4];
                    ldsm_x4(q, Bs + (nt2 * 16 + ((lane >> 4) & 1) * 8 + (lane & 7))
                                      * B_ROWH + kOffB + ks * 16);
                    mma16816(acc[2 * nt2],     buf + ks * 4, q);
                    mma16816(acc[2 * nt2 + 1], buf + ks * 4, q + 2);
                }
            }
        };

        ldA(0, ab[0]); ldA(1, ab[1]); ldA(2, ab[2]);
        mmaC(ab[0], 0);
        ldA(3, ab[0]);                   // reuse buf 0 (chunk-0 MMAs already issued)
        mmaC(ab[1], 1);
        mmaC(ab[2], 2);
        mmaC(ab[0], 3);

        // ---- store K-partials: part[r][c][kw] ----
        #pragma unroll
        for (int nt = 0; nt < 8; nt++)
            #pragma unroll
            for (int e = 0; e < 4; e++) {
                int r = ms * 16 + (lane >> 2) + (e >> 1) * 8;
                int c = nt * 8 + (lane & 3) * 2 + (e & 1);
                part[(r * 65 + c) * 4 + kw] = acc[nt][e];
            }
        __syncthreads();                                   // S2: partials published

        // ---- reduce (LDS.128) + gate + state update: 2 elements/thread ----
        const float4* p4 = reinterpret_cast<const float4*>(part);
        #pragma unroll
        for (int rep = 0; rep < 2; rep++) {
            const int lr = rep ? lr1 : lr0;
            const int bb = rep ? bb1 : bb0;
            const int tk = rep ? tk1 : tk0;

            float4 vi = p4[lr * 65 + j];
            float4 vf = p4[lr * 65 + 16 + j];
            float4 vg = p4[lr * 65 + 32 + j];
            float4 vo = p4[lr * 65 + 48 + j];

            float zi = ((vi.x + vi.y) + (vi.z + vi.w)) + (rep ? ew1i : ew0i);
            float zf = ((vf.x + vf.y) + (vf.z + vf.w)) + (rep ? ew1f : ew0f);
            float zg = ((vg.x + vg.y) + (vg.z + vg.w)) + (rep ? ew1g : ew0g);
            float zo = ((vo.x + vo.y) + (vo.z + vo.w)) + (rep ? ew1o : ew0o);

            float ig = fsig(zi);
            float fg = fsig(zf);
            float gg = ftanh(zg);
            float og = fsig(zo);

            float cp = c_reg[rep];
            float cn = fg * cp + ig * gg;
            float hn = og * ftanh(cn);

            bool msk = (tk != 0);
            float ho = msk ? hn : h_reg[rep];
            float co = msk ? cn : cp;

            c_reg[rep] = co;
            h_reg[rep] = ho;
            d_S[((size_t)bb * TSEQ + t) * HDIM + col] = ho;
            d_A16[wb][bb * HDIM + pcol] = __float2half_rn(ho);   // permuted store
        }

        // ---- release: h(t) of (my batch half, my quarter) published ----
        __syncthreads();                                   // S3: all h stores done
        if (tid == 0) {
            asm volatile("red.release.gpu.global.add.u32 [%0], 1;"
                         :: "l"(&g_qcnt[bg * 4 + myq]) : "memory");
        }
    }
}

// ---------------- decode + softmax ----------------
__global__ void __launch_bounds__(256) decode_kernel(const float* __restrict__ Wd,
                                                     const float* __restrict__ bd,
                                                     float* __restrict__ out) {
    __shared__ float s[64][33];
    __shared__ float w[32][128];
    const int row0 = blockIdx.x * 64;
    const int tid  = threadIdx.x;
    const int r    = tid >> 2;
    const int q    = tid & 3;

    float acc[32];
    #pragma unroll
    for (int i = 0; i < 32; i++) acc[i] = 0.f;

    for (int kt = 0; kt < 32; kt++) {
        for (int i = tid; i < 64 * 32; i += 256) {
            int rr = i >> 5, kk = i & 31;
            s[rr][kk] = d_S[(size_t)(row0 + rr) * HDIM + kt * 32 + kk];
        }
        for (int i = tid; i < 32 * 128; i += 256) {
            int kk = i >> 7, cc = i & 127;
            w[kk][cc] = Wd[(size_t)(kt * 32 + kk) * VOC + cc];
        }
        __syncthreads();

        #pragma unroll 4
        for (int kk = 0; kk < 32; kk++) {
            float sv = s[r][kk];
            const float4* wrow = reinterpret_cast<const float4*>(&w[kk][q * 32]);
            #pragma unroll
            for (int c4 = 0; c4 < 8; c4++) {
                float4 wv = wrow[c4];
                acc[c4 * 4 + 0] += sv * wv.x;
                acc[c4 * 4 + 1] += sv * wv.y;
                acc[c4 * 4 + 2] += sv * wv.z;
                acc[c4 * 4 + 3] += sv * wv.w;
            }
        }
        __syncthreads();
    }

    float m = -1e30f;
    #pragma unroll
    for (int c = 0; c < 32; c++) {
        acc[c] += bd[q * 32 + c];
        m = fmaxf(m, acc[c]);
    }
    m = fmaxf(m, __shfl_xor_sync(0xFFFFFFFFu, m, 1));
    m = fmaxf(m, __shfl_xor_sync(0xFFFFFFFFu, m, 2));

    float sum = 0.f;
    #pragma unroll
    for (int c = 0; c < 32; c++) {
        acc[c] = expf(acc[c] - m);
        sum += acc[c];
    }
    sum += __shfl_xor_sync(0xFFFFFFFFu, sum, 1);
    sum += __shfl_xor_sync(0xFFFFFFFFu, sum, 2);
    float inv = 1.0f / sum;

    float* orow = out + (size_t)(row0 + r) * VOC + q * 32;
    #pragma unroll
    for (int c4 = 0; c4 < 8; c4++) {
        float4 v;
        v.x = acc[c4 * 4 + 0] * inv;
        v.y = acc[c4 * 4 + 1] * inv;
        v.z = acc[c4 * 4 + 2] * inv;
        v.w = acc[c4 * 4 + 3] * inv;
        reinterpret_cast<float4*>(orow)[c4] = v;
    }
}

// ---------------- launcher ----------------
extern "C" void kernel_launch(void* const* d_in, const int* in_sizes, int n_in,
                              void* d_out, int out_size) {
    (void)in_sizes; (void)n_in; (void)out_size;
    const int*   tokens = (const int*)  d_in[0];
    const float* emb    = (const float*)d_in[1];
    const float* W      = (const float*)d_in[2];
    const float* U      = (const float*)d_in[3];
    const float* b      = (const float*)d_in[4];
    const float* Wd     = (const float*)d_in[5];
    const float* bd     = (const float*)d_in[6];
    float* out = (float*)d_out;

    cudaFuncSetAttribute(lstm_persist, cudaFuncAttributeMaxDynamicSharedMemorySize,
                         SMEM_TOTAL);

    prep_embW<<<128, 256>>>(emb, W, b);
    prep_U<<<dim3(128, 32), 256>>>(U);
    init_state<<<512, 256>>>();
    lstm_persist<<<NBLK, 512, SMEM_TOTAL>>>(tokens);
    decode_kernel<<<1024, 256>>>(Wd, bd, out);
}

// round 17
// speedup vs baseline: 1.0699x; 1.0699x over previous
#include <cuda_runtime.h>
#include <cuda_fp16.h>
#include <cstdint>
#include <cstddef>

#define TSEQ 512
#define BATCH 128
#define HDIM 1024
#define NZ 4096
#define VOC 128
#define EDIM 256
#define NBLK 128

// ---------------- static device buffers ----------------
__device__ half  d_U16[(size_t)NZ * HDIM];            // U^T fp16 [n][k], 8 MB
__device__ float d_embW[VOC * NZ];                    // emb@W + b  [v][n], 2 MB
__device__ half  d_A16[2][BATCH * HDIM];              // ping-pong h (fp16)
__device__ float d_S[(size_t)BATCH * TSEQ * HDIM];    // fp32 states, 256 MB
__device__ unsigned g_qcnt[8];                        // [bg][kw] release counters

// ---------------- PTX helpers ----------------
__device__ __forceinline__ unsigned smaddr(const void* p) {
    return (unsigned)__cvta_generic_to_shared(p);
}
__device__ __forceinline__ void cpa16(void* dst, const void* src) {
    asm volatile("cp.async.cg.shared.global [%0], [%1], 16;\n"
                 :: "r"(smaddr(dst)), "l"(src));
}
__device__ __forceinline__ void ldsm_x4(unsigned* r, const void* p) {
    unsigned a = smaddr(p);
    asm volatile("ldmatrix.sync.aligned.m8n8.x4.shared.b16 {%0,%1,%2,%3}, [%4];\n"
                 : "=r"(r[0]), "=r"(r[1]), "=r"(r[2]), "=r"(r[3]) : "r"(a));
}
__device__ __forceinline__ void mma16816(float* d, const unsigned* a, const unsigned* b) {
    asm volatile("mma.sync.aligned.m16n8k16.row.col.f32.f16.f16.f32 "
                 "{%0,%1,%2,%3},{%4,%5,%6,%7},{%8,%9},{%0,%1,%2,%3};\n"
                 : "+f"(d[0]), "+f"(d[1]), "+f"(d[2]), "+f"(d[3])
                 : "r"(a[0]), "r"(a[1]), "r"(a[2]), "r"(a[3]),
                   "r"(b[0]), "r"(b[1]));
}
// ---- fast activations: single-instruction MUFU.TANH ----
__device__ __forceinline__ float ftanh(float x) {
    float r; asm("tanh.approx.f32 %0, %1;" : "=f"(r) : "f"(x)); return r;
}
__device__ __forceinline__ float fsig(float x) {
    float r; asm("tanh.approx.f32 %0, %1;" : "=f"(r) : "f"(0.5f * x));
    return fmaf(0.5f, r, 0.5f);
}

// ---------------- prep: embW = emb @ W + b   (128 x 4096, K=256) ----------------
__global__ void __launch_bounds__(256) prep_embW(const float* __restrict__ emb,
                                                 const float* __restrict__ W,
                                                 const float* __restrict__ bias) {
    __shared__ float Ws[EDIM][32];
    const int n0 = blockIdx.x * 32;
    for (int i = threadIdx.x; i < EDIM * 32; i += 256) {
        int e = i >> 5, c = i & 31;
        Ws[e][c] = W[(size_t)e * NZ + n0 + c];
    }
    __syncthreads();
    const int c = threadIdx.x & 31;
    for (int v = threadIdx.x >> 5; v < VOC; v += 8) {
        float a = bias[n0 + c];
        const float* er = emb + v * EDIM;
        #pragma unroll 8
        for (int e = 0; e < EDIM; e++) a += er[e] * Ws[e][c];
        d_embW[v * NZ + n0 + c] = a;
    }
}

// ---------------- prep: U fp32 [k][n] -> d_U16 fp16 [n][k] ----------------
__global__ void __launch_bounds__(256) prep_U(const float* __restrict__ U) {
    __shared__ float tile[32][33];
    const int n0 = blockIdx.x * 32;
    const int k0 = blockIdx.y * 32;
    const int tx = threadIdx.x & 31, ty = threadIdx.x >> 5;
    #pragma unroll
    for (int i = 0; i < 4; i++) {
        int r = ty + i * 8;
        tile[r][tx] = U[(size_t)(k0 + r) * NZ + n0 + tx];
    }
    __syncthreads();
    #pragma unroll
    for (int i = 0; i < 4; i++) {
        int r = ty + i * 8;
        d_U16[(size_t)(n0 + r) * HDIM + k0 + tx] = __float2half_rn(tile[tx][r]);
    }
}

__global__ void init_state() {
    int i = blockIdx.x * blockDim.x + threadIdx.x;
    if (i < BATCH * HDIM) d_A16[0][i] = __float2half_rn(0.f);
    if (blockIdx.x == 0 && threadIdx.x < 8) g_qcnt[threadIdx.x] = 0;
}

// ---------------- persistent LSTM: 64 n-groups x 2 batch-halves ----------------
// Block (ng = bn & 63, bg = bn >> 6) owns batch rows [64bg,64bg+64) x h-cols
// [16ng,16ng+16) => z-cols {g*1024 + 16ng + j}. 16 warps = 4 M-subs (16 rows)
// x 4 K-slices. Warp-private 2-stage A rings, no mainloop barriers.
// Sync: counters [bg][kw]; producer (ng,bg) releases [bg][ng>>4]; target 16/step.
#define KC 64
#define B_ROWH 1032                             // 1024 + 8 pad halfs
#define B_H    (64 * B_ROWH)                    // 66048 halfs = 132096 B
#define A_STG_H (16 * 72)                       // 1152 halfs = 2304 B per stage
#define SMEM_TOTAL ((B_H + 16 * 2 * A_STG_H) * 2)   // 132096 + 73728 = 205824 B

__global__ void __launch_bounds__(512, 1) lstm_persist(const int* __restrict__ tokens) {
    extern __shared__ __align__(16) half smh[];
    half*  Bs   = smh;                                   // B[64][1032]
    float* part = reinterpret_cast<float*>(smh + B_H);   // [64][65][4] = 66560 B

    const int tid  = threadIdx.x;
    const int bn   = blockIdx.x;
    const int ng   = bn & 63;      // n-group: h-cols [16ng, 16ng+16)
    const int bg   = bn >> 6;      // batch half: rows [64bg, 64bg+64)
    const int lane = tid & 31, wid = tid >> 5;
    const int ms   = wid & 3;      // M-sub: local rows [ms*16, ms*16+16)
    const int kw   = wid >> 2;     // K-slice: k in [kw*256, kw*256+256)
    const int myq  = ng >> 4;      // k-quarter this block's h-cols land in

    half* Aw = smh + B_H + wid * (2 * A_STG_H);          // private 2-stage ring

    // ---- c/h in registers; thread owns 2 elements, fixed for all steps ----
    const int j    = tid & 15;
    const int lr0  = tid >> 4;                 // 0..31
    const int lr1  = lr0 + 32;                 // 32..63
    const int bb0  = bg * 64 + lr0;
    const int bb1  = bg * 64 + lr1;
    const int col  = ng * 16 + j;              // global h-col
    float c_reg[2] = {0.f, 0.f};
    float h_reg[2] = {0.f, 0.f};

    // ---- B preload ONCE: 64 z-cols x 1024 k = 8192 x 16B ----
    #pragma unroll
    for (int w = 0; w < 16; w++) {
        int i = tid + w * 512;                 // 0..8191
        int ci = i >> 7, seg = i & 127;
        int gcol = (ci >> 4) * HDIM + ng * 16 + (ci & 15);
        cpa16(Bs + ci * B_ROWH + seg * 8, d_U16 + (size_t)gcol * HDIM + seg * 8);
    }
    asm volatile("cp.async.commit_group;\ncp.async.wait_group 0;\n");
    __syncthreads();

    const int aRowL = (lane & 7) + ((lane >> 3) & 1) * 8;
    const int aCol  = ((lane >> 4) & 1) * 8;
    const int bKsel = ((lane >> 3) & 1) * 8;
    // ldsm_x4 B row: matrices {nt2 rows, nt2 rows, nt2+1 rows, nt2+1 rows} x k halves
    const int bRowX4 = ((lane >> 4) & 1) * 8 + (lane & 7);

    for (int t = 0; t < TSEQ; t++) {
        const int rb = t & 1, wb = rb ^ 1;
        const half* __restrict__ Asrc = d_A16[rb];

        // ---- prefetch gate inputs (independent of h) ----
        const int tk0 = __ldg(&tokens[bb0 * TSEQ + t]);
        const int tk1 = __ldg(&tokens[bb1 * TSEQ + t]);
        const float* e0 = d_embW + (size_t)tk0 * NZ + col;
        const float* e1 = d_embW + (size_t)tk1 * NZ + col;
        float ew0i = e0[0], ew0f = e0[HDIM], ew0g = e0[2 * HDIM], ew0o = e0[3 * HDIM];
        float ew1i = e1[0], ew1f = e1[HDIM], ew1g = e1[2 * HDIM], ew1o = e1[3 * HDIM];

        // ---- acquire own (bg, kw): h(t-1) rows of my half, quarter kw ready ----
        if (lane == 0) {
            const unsigned target = 16u * (unsigned)t;
            unsigned v;
            asm volatile("ld.acquire.gpu.global.u32 %0, [%1];"
                         : "=r"(v) : "l"(&g_qcnt[bg * 4 + kw]) : "memory");
            while (v < target) {
                __nanosleep(64);
                asm volatile("ld.acquire.gpu.global.u32 %0, [%1];"
                             : "=r"(v) : "l"(&g_qcnt[bg * 4 + kw]) : "memory");
            }
        }
        __syncwarp();

        // warp-private A loader: 16 rows x 64 k = 128 x 16B, 4 cpa16/lane
        auto load_A = [&](int ch) {
            half* st = Aw + (ch & 1) * A_STG_H;
            const int k0 = kw * 256 + ch * KC;
            #pragma unroll
            for (int w = 0; w < 4; w++) {
                int i = lane + w * 32;                    // 0..127
                int row = i >> 3, seg = i & 7;
                cpa16(st + row * 72 + seg * 8,
                      Asrc + (size_t)(bg * 64 + ms * 16 + row) * HDIM + k0 + seg * 8);
            }
            asm volatile("cp.async.commit_group;\n");
        };
        load_A(0); load_A(1);

        float acc[8][4];
        #pragma unroll
        for (int n = 0; n < 8; n++)
            #pragma unroll
            for (int e = 0; e < 4; e++) acc[n][e] = 0.f;

        for (int ch = 0; ch < 4; ch++) {
            asm volatile("cp.async.wait_group 1;\n");     // chunk ch resident (private)

            const half* st = Aw + (ch & 1) * A_STG_H;
            const int kOffB = kw * 256 + ch * KC + bKsel;
            #pragma unroll
            for (int ks = 0; ks < 4; ks++) {
                unsigned af[4];
                ldsm_x4(af, st + aRowL * 72 + aCol + ks * 16);
                #pragma unroll
                for (int nt2 = 0; nt2 < 4; nt2++) {
                    unsigned q[4];
                    ldsm_x4(q, Bs + (nt2 * 16 + bRowX4) * B_ROWH
                                   + kOffB + ks * 16);
                    mma16816(acc[2 * nt2],     af, q);
                    mma16816(acc[2 * nt2 + 1], af, q + 2);
                }
            }

            if (ch < 2) load_A(ch + 2);                   // slot freed: MMAs issued
            else asm volatile("cp.async.commit_group;\n");
        }
        asm volatile("cp.async.wait_group 0;\n");
        __syncthreads();                                   // S1: all GEMM reads done

        // ---- store K-partials: part[r][c][kw], r<64 local row, c<64 z-col ----
        #pragma unroll
        for (int nt = 0; nt < 8; nt++)
            #pragma unroll
            for (int e = 0; e < 4; e++) {
                int r = ms * 16 + (lane >> 2) + (e >> 1) * 8;
                int c = nt * 8 + (lane & 3) * 2 + (e & 1);
                part[(r * 65 + c) * 4 + kw] = acc[nt][e];
            }
        __syncthreads();                                   // S2: partials published

        // ---- reduce (LDS.128) + gate + state update: 2 elements/thread ----
        const float4* p4 = reinterpret_cast<const float4*>(part);
        #pragma unroll
        for (int rep = 0; rep < 2; rep++) {
            const int lr = rep ? lr1 : lr0;
            const int bb = rep ? bb1 : bb0;
            const int tk = rep ? tk1 : tk0;

            float4 vi = p4[lr * 65 + j];
            float4 vf = p4[lr * 65 + 16 + j];
            float4 vg = p4[lr * 65 + 32 + j];
            float4 vo = p4[lr * 65 + 48 + j];

            float zi = ((vi.x + vi.y) + (vi.z + vi.w)) + (rep ? ew1i : ew0i);
            float zf = ((vf.x + vf.y) + (vf.z + vf.w)) + (rep ? ew1f : ew0f);
            float zg = ((vg.x + vg.y) + (vg.z + vg.w)) + (rep ? ew1g : ew0g);
            float zo = ((vo.x + vo.y) + (vo.z + vo.w)) + (rep ? ew1o : ew0o);

            float ig = fsig(zi);
            float fg = fsig(zf);
            float gg = ftanh(zg);
            float og = fsig(zo);

            float cp = c_reg[rep];
            float cn = fg * cp + ig * gg;
            float hn = og * ftanh(cn);

            bool msk = (tk != 0);
            float ho = msk ? hn : h_reg[rep];
            float co = msk ? cn : cp;

            c_reg[rep] = co;
            h_reg[rep] = ho;
            d_S[((size_t)bb * TSEQ + t) * HDIM + col] = ho;
            d_A16[wb][bb * HDIM + col] = __float2half_rn(ho);
        }

        // ---- release: h(t) of (my batch half, my quarter) published ----
        __syncthreads();                                   // S3: all h stores done
        if (tid == 0) {
            asm volatile("red.release.gpu.global.add.u32 [%0], 1;"
                         :: "l"(&g_qcnt[bg * 4 + myq]) : "memory");
        }
    }
}

// ---------------- decode + softmax ----------------
__global__ void __launch_bounds__(256) decode_kernel(const float* __restrict__ Wd,
                                                     const float* __restrict__ bd,
                                                     float* __restrict__ out) {
    __shared__ float s[64][33];
    __shared__ float w[32][128];
    const int row0 = blockIdx.x * 64;
    const int tid  = threadIdx.x;
    const int r    = tid >> 2;
    const int q    = tid & 3;

    float acc[32];
    #pragma unroll
    for (int i = 0; i < 32; i++) acc[i] = 0.f;

    for (int kt = 0; kt < 32; kt++) {
        for (int i = tid; i < 64 * 32; i += 256) {
            int rr = i >> 5, kk = i & 31;
            s[rr][kk] = d_S[(size_t)(row0 + rr) * HDIM + kt * 32 + kk];
        }
        for (int i = tid; i < 32 * 128; i += 256) {
            int kk = i >> 7, cc = i & 127;
            w[kk][cc] = Wd[(size_t)(kt * 32 + kk) * VOC + cc];
        }
        __syncthreads();

        #pragma unroll 4
        for (int kk = 0; kk < 32; kk++) {
            float sv = s[r][kk];
            const float4* wrow = reinterpret_cast<const float4*>(&w[kk][q * 32]);
            #pragma unroll
            for (int c4 = 0; c4 < 8; c4++) {
                float4 wv = wrow[c4];
                acc[c4 * 4 + 0] += sv * wv.x;
                acc[c4 * 4 + 1] += sv * wv.y;
                acc[c4 * 4 + 2] += sv * wv.z;
                acc[c4 * 4 + 3] += sv * wv.w;
            }
        }
        __syncthreads();
    }

    float m = -1e30f;
    #pragma unroll
    for (int c = 0; c < 32; c++) {
        acc[c] += bd[q * 32 + c];
        m = fmaxf(m, acc[c]);
    }
    m = fmaxf(m, __shfl_xor_sync(0xFFFFFFFFu, m, 1));
    m = fmaxf(m, __shfl_xor_sync(0xFFFFFFFFu, m, 2));

    float sum = 0.f;
    #pragma unroll
    for (int c = 0; c < 32; c++) {
        acc[c] = expf(acc[c] - m);
        sum += acc[c];
    }
    sum += __shfl_xor_sync(0xFFFFFFFFu, sum, 1);
    sum += __shfl_xor_sync(0xFFFFFFFFu, sum, 2);
    float inv = 1.0f / sum;

    float* orow = out + (size_t)(row0 + r) * VOC + q * 32;
    #pragma unroll
    for (int c4 = 0; c4 < 8; c4++) {
        float4 v;
        v.x = acc[c4 * 4 + 0] * inv;
        v.y = acc[c4 * 4 + 1] * inv;
        v.z = acc[c4 * 4 + 2] * inv;
        v.w = acc[c4 * 4 + 3] * inv;
        reinterpret_cast<float4*>(orow)[c4] = v;
    }
}

// ---------------- launcher ----------------
extern "C" void kernel_launch(void* const* d_in, const int* in_sizes, int n_in,
                              void* d_out, int out_size) {
    (void)in_sizes; (void)n_in; (void)out_size;
    const int*   tokens = (const int*)  d_in[0];
    const float* emb    = (const float*)d_in[1];
    const float* W      = (const float*)d_in[2];
    const float* U      = (const float*)d_in[3];
    const float* b      = (const float*)d_in[4];
    const float* Wd     = (const float*)d_in[5];
    const float* bd     = (const float*)d_in[6];
    float* out = (float*)d_out;

    cudaFuncSetAttribute(lstm_persist, cudaFuncAttributeMaxDynamicSharedMemorySize,
                         SMEM_TOTAL);

    prep_embW<<<128, 256>>>(emb, W, b);
    prep_U<<<dim3(128, 32), 256>>>(U);
    init_state<<<512, 256>>>();
    lstm_persist<<<NBLK, 512, SMEM_TOTAL>>>(tokens);
    decode_kernel<<<1024, 256>>>(Wd, bd, out);
}